// round 13
// baseline (speedup 1.0000x reference)
#include <cuda_runtime.h>
#include <cuda_bf16.h>
#include <cstdint>

// Fused LSTM (Keras gates i,f,g,o; relu cell activation) + dense(10) + softmax.
// B=16384, T=28, F=28, H=128. One block owns RTILE=32 batch rows for all
// timesteps. FFMA2 (fma.rn.f32x2) packed over adjacent UNIT pairs; weight
// pairs are contiguous LDG.64 from original W/U; h/x stored duplicated (v,v)
// in shared, read as LDS.128 giving TWO rows' packs per instruction.
// vs measured round-11 (2257 us, L1=61.5%, issue=44%): halves L1 wavefronts
// per FFMA2 and halves L2 weight traffic. Cold-state register trims to avoid
// spilling under the 128-reg cap.

#define HCELLS 128
#define G4     512      // 4*H
#define RTILE  32       // batch rows per block
#define RTP    34       // padded row stride: 34*8B=272B=16*17 -> LDS.128 aligned
#define RP     8        // rows per thread (4 groups of 64 threads)
#define NKP    64       // unit-pairs (2 units per thread)
#define TSTEPS 28
#define FDIM   28
#define NCLS   10
#define XTOT   (RTILE * FDIM)   // 896 staged x values per step
#define TF     (TSTEPS * FDIM)  // 784

typedef unsigned long long ull;

__device__ __forceinline__ float sigm(float z) { return 1.0f / (1.0f + __expf(-z)); }

__device__ __forceinline__ void ffma2(ull& acc, ull a, ull b) {
    asm("fma.rn.f32x2 %0, %1, %2, %0;" : "+l"(acc) : "l"(a), "l"(b));
}
__device__ __forceinline__ float lo32(ull v) { return __uint_as_float((unsigned)(v & 0xFFFFFFFFull)); }
__device__ __forceinline__ float hi32(ull v) { return __uint_as_float((unsigned)(v >> 32)); }

__global__ __launch_bounds__(256, 2)
void lstm_fused(const float* __restrict__ x, const float* __restrict__ W,
                const float* __restrict__ U, const float* __restrict__ b,
                const float* __restrict__ Wd, const float* __restrict__ bd,
                float* __restrict__ out)
{
    __shared__ float2 hsh[HCELLS][RTP];  // [unit][row] = (h,h) duplicated
    __shared__ float2 xsh[FDIM][RTP];    // [feat][row] = (x,x) duplicated

    const int tid   = threadIdx.x;
    const int kp    = tid & (NKP - 1);    // unit-pair id: owns units 2kp, 2kp+1
    const int grp   = tid >> 6;           // row group 0..3
    const int rbase = grp * RP;           // multiple of 8 -> LDS.128 alignment holds
    const long row0 = (long)blockIdx.x * RTILE;

    // x staging: 896 values / 256 threads. Slots 0..2 always valid; slot 3 iff tid<128.
    // goff[s]: offset of element (row r, feat f) from x+row0*TF; soff[s]: smem float2 index.
    const float* xbase = x + row0 * TF;
    int goff[4], soff[4];
    #pragma unroll
    for (int s = 0; s < 4; s++) {
        const int idx = tid + 256 * s;          // may be >= XTOT only for s==3
        const int r = idx / FDIM, f = idx % FDIM;
        goff[s] = r * TF + f;
        soff[s] = f * RTP + r;
    }
    const bool has3 = (tid < XTOT - 768);       // tid < 128

    // init h = 0
    for (int i = tid; i < HCELLS * RTP; i += 256)
        (&hsh[0][0])[i] = make_float2(0.0f, 0.0f);
    // preload x[:, t=0, :] duplicated
    #pragma unroll
    for (int s = 0; s < 3; s++) {
        float v = xbase[goff[s]];
        (&xsh[0][0])[soff[s]] = make_float2(v, v);
    }
    if (has3) {
        float v = xbase[goff[3]];
        (&xsh[0][0])[soff[3]] = make_float2(v, v);
    }

    float c[RP][2];
    #pragma unroll
    for (int r = 0; r < RP; r++) { c[r][0] = 0.0f; c[r][1] = 0.0f; }

    // bias pairs (contiguous, 8B-aligned since 2kp is even)
    ull bz[4];
    #pragma unroll
    for (int g = 0; g < 4; g++)
        bz[g] = *(const ull*)&b[g * HCELLS + 2 * kp];

    const float* Wp = W + 2 * kp;   // W: [FDIM][G4] row-major
    const float* Up = U + 2 * kp;   // U: [HCELLS][G4] row-major

    __syncthreads();

    for (int t = 0; t < TSTEPS; t++) {
        // prefetch next-step x into registers; W+U compute hides the latency
        float xp[4];
        if (t < TSTEPS - 1) {
            const float* xb = xbase + (t + 1) * FDIM;
            xp[0] = xb[goff[0]];
            xp[1] = xb[goff[1]];
            xp[2] = xb[goff[2]];
            xp[3] = has3 ? xb[goff[3]] : 0.0f;
        }

        ull ai[RP], af[RP], ag[RP], ao[RP];
        #pragma unroll
        for (int r = 0; r < RP; r++) { ai[r] = bz[0]; af[r] = bz[1]; ag[r] = bz[2]; ao[r] = bz[3]; }

        // z += x_t @ W  (F=28 inner dim)
        #pragma unroll 2
        for (int f = 0; f < FDIM; f++) {
            const ull w0 = *(const ull*)&Wp[f * G4];
            const ull w1 = *(const ull*)&Wp[f * G4 + 128];
            const ull w2 = *(const ull*)&Wp[f * G4 + 256];
            const ull w3 = *(const ull*)&Wp[f * G4 + 384];
            #pragma unroll
            for (int p = 0; p < RP / 2; p++) {
                // one LDS.128 broadcast -> (x,x) packs for rows rbase+2p, rbase+2p+1
                const ulonglong2 xv = *(const ulonglong2*)&xsh[f][rbase + 2 * p];
                ffma2(ai[2 * p], xv.x, w0);  ffma2(ai[2 * p + 1], xv.y, w0);
                ffma2(af[2 * p], xv.x, w1);  ffma2(af[2 * p + 1], xv.y, w1);
                ffma2(ag[2 * p], xv.x, w2);  ffma2(ag[2 * p + 1], xv.y, w2);
                ffma2(ao[2 * p], xv.x, w3);  ffma2(ao[2 * p + 1], xv.y, w3);
            }
        }

        // z += h @ U  (H=128 inner dim)
        #pragma unroll 2
        for (int j = 0; j < HCELLS; j++) {
            const ull u0 = *(const ull*)&Up[j * G4];
            const ull u1 = *(const ull*)&Up[j * G4 + 128];
            const ull u2 = *(const ull*)&Up[j * G4 + 256];
            const ull u3 = *(const ull*)&Up[j * G4 + 384];
            #pragma unroll
            for (int p = 0; p < RP / 2; p++) {
                const ulonglong2 hv = *(const ulonglong2*)&hsh[j][rbase + 2 * p];
                ffma2(ai[2 * p], hv.x, u0);  ffma2(ai[2 * p + 1], hv.y, u0);
                ffma2(af[2 * p], hv.x, u1);  ffma2(af[2 * p + 1], hv.y, u1);
                ffma2(ag[2 * p], hv.x, u2);  ffma2(ag[2 * p + 1], hv.y, u2);
                ffma2(ao[2 * p], hv.x, u3);  ffma2(ao[2 * p + 1], hv.y, u3);
            }
        }

        __syncthreads();   // all reads of old h / current x complete

        // gates + state update; write new h (same buffer, post-barrier)
        #pragma unroll
        for (int r = 0; r < RP; r++) {
            #pragma unroll
            for (int s = 0; s < 2; s++) {     // s=0 -> unit 2kp, s=1 -> unit 2kp+1
                const float zi = s ? hi32(ai[r]) : lo32(ai[r]);
                const float zf = s ? hi32(af[r]) : lo32(af[r]);
                const float zg = s ? hi32(ag[r]) : lo32(ag[r]);
                const float zo = s ? hi32(ao[r]) : lo32(ao[r]);
                const float ig = sigm(zi);
                const float fg = sigm(zf);
                const float gg = fmaxf(zg, 0.0f);             // relu candidate
                const float og = sigm(zo);
                const float cn = fmaf(fg, c[r][s], ig * gg);
                c[r][s] = cn;
                const float hn = og * fmaxf(cn, 0.0f);        // relu cell activation
                hsh[2 * kp + s][rbase + r] = make_float2(hn, hn);
            }
        }

        // commit prefetched x for next timestep
        if (t < TSTEPS - 1) {
            (&xsh[0][0])[soff[0]] = make_float2(xp[0], xp[0]);
            (&xsh[0][0])[soff[1]] = make_float2(xp[1], xp[1]);
            (&xsh[0][0])[soff[2]] = make_float2(xp[2], xp[2]);
            if (has3) (&xsh[0][0])[soff[3]] = make_float2(xp[3], xp[3]);
        }

        __syncthreads();   // publish h/x for next step
    }

    // epilogue: logits = h @ Wd + bd, softmax (tiny; one thread per row)
    if (tid < RTILE) {
        const int r = tid;
        float logit[NCLS];
        #pragma unroll
        for (int d = 0; d < NCLS; d++) logit[d] = bd[d];
        for (int kk = 0; kk < HCELLS; kk++) {
            const float hv = hsh[kk][r].x;
            #pragma unroll
            for (int d = 0; d < NCLS; d++)
                logit[d] = fmaf(hv, Wd[kk * NCLS + d], logit[d]);
        }
        float m = logit[0];
        #pragma unroll
        for (int d = 1; d < NCLS; d++) m = fmaxf(m, logit[d]);
        float s = 0.0f;
        #pragma unroll
        for (int d = 0; d < NCLS; d++) { logit[d] = __expf(logit[d] - m); s += logit[d]; }
        const float inv = 1.0f / s;
        #pragma unroll
        for (int d = 0; d < NCLS; d++) out[(row0 + r) * NCLS + d] = logit[d] * inv;
    }
}

extern "C" void kernel_launch(void* const* d_in, const int* in_sizes, int n_in,
                              void* d_out, int out_size) {
    const float* x  = (const float*)d_in[0];
    const float* W  = (const float*)d_in[1];
    const float* U  = (const float*)d_in[2];
    const float* b  = (const float*)d_in[3];
    const float* Wd = (const float*)d_in[4];
    const float* bd = (const float*)d_in[5];
    float* out = (float*)d_out;

    const int B = in_sizes[0] / TF;   // 16384
    lstm_fused<<<B / RTILE, 256>>>(x, W, U, b, Wd, bd, out);
}